// round 7
// baseline (speedup 1.0000x reference)
#include <cuda_runtime.h>
#include <math.h>

// RNN_472446402977: 4-layer tanh RNN + FC, fp32. B=512 S=256 D_IN=28 H=128 NC=10.
// R7: recurrence with j-split over 2 warp-groups (256 thr/CTA -> 2 warps/SMSP,
// half-length FMA2 chains, latency hidden), lane-split partial reduction.
// Projections: register-tiled 128x128 f32x2 GEMM (unchanged from R6).

#define BB 512
#define SS 256
#define DIN 28
#define HH 128
#define NC 10

typedef unsigned long long u64;

// Scratch (allocation-free): each [S][B][H] fp32 = 64MB.
__device__ float g_bufA[SS * BB * HH];
__device__ float g_bufB[SS * BB * HH];
__device__ float g_bufC[SS * BB * HH];

// ---- packed f32x2 helpers -------------------------------------------------
#define FMA2(acc, a, b) asm("fma.rn.f32x2 %0, %1, %2, %0;" : "+l"(acc) : "l"(a), "l"(b))
#define ADD2(acc, a)    asm("add.rn.f32x2 %0, %0, %1;"     : "+l"(acc) : "l"(a))

__device__ __forceinline__ u64 pk(float lo, float hi) {
    u64 r; asm("mov.b64 %0, {%1, %2};" : "=l"(r) : "f"(lo), "f"(hi)); return r;
}
__device__ __forceinline__ void upk(u64 v, float& lo, float& hi) {
    asm("mov.b64 {%0, %1}, %2;" : "=f"(lo), "=f"(hi) : "l"(v));
}

// Accurate tanh regardless of fast-math mapping of tanhf (~1e-6 rel).
__device__ __forceinline__ float my_tanh(float x) {
    float ax = fabsf(x);
    float e  = __expf(-2.0f * ax);
    float r  = (1.0f - e) / (1.0f + e);
    return copysignf(r, x);
}

// ---------------------------------------------------------------------------
// Projection GEMM: out[row][n] = sum_k A[row][k]*W[n][k] + (b1[n]+b2[n])
// 128x128 tile per CTA, 256 threads, 8x8 outputs/thread, f32x2 row-pair accs.
// ---------------------------------------------------------------------------
template <int K, int KC, bool SWAPPED>
__global__ __launch_bounds__(256, 2)
void proj_kernel(const float* __restrict__ A, const float* __restrict__ W,
                 const float* __restrict__ b1, const float* __restrict__ b2,
                 float* __restrict__ out) {
    extern __shared__ float sm[];
    float* Ws = sm;               // [K][132]   Ws[k][n] = W[n][k]
    float* As = sm + K * 132;     // [KC][132]  As[k][m]
    __shared__ float bs[HH];

    const int tid = threadIdx.x;

    for (int idx = tid; idx < HH * K; idx += 256) {
        int n = idx / K, k = idx - n * K;
        Ws[k * 132 + n] = W[idx];
    }
    if (tid < HH) bs[tid] = b1[tid] + b2[tid];

    const int mg = tid & 15, ng = tid >> 4;
    const int c0 = ng * 8;
    const int row0 = blockIdx.x * 128;

    __syncthreads();

    u64 acc[4][8];
#pragma unroll
    for (int c = 0; c < 8; c++) {
        float bv = bs[c0 + c];
        u64 p = pk(bv, bv);
        acc[0][c] = p; acc[1][c] = p; acc[2][c] = p; acc[3][c] = p;
    }

    for (int kc = 0; kc < K; kc += KC) {
        __syncthreads();
        for (int idx = tid; idx < 128 * (KC / 4); idx += 256) {
            int m  = idx / (KC / 4);
            int kq = idx - m * (KC / 4);
            int row = row0 + m;
            const float* src;
            if (SWAPPED) {
                int t = row >> 9, b = row & 511;   // rows are t*B+b, x is [B][S][D]
                src = A + (b * SS + t) * K + kc + 4 * kq;
            } else {
                src = A + (size_t)row * K + kc + 4 * kq;
            }
            float4 v = *(const float4*)src;
            As[(4 * kq + 0) * 132 + m] = v.x;
            As[(4 * kq + 1) * 132 + m] = v.y;
            As[(4 * kq + 2) * 132 + m] = v.z;
            As[(4 * kq + 3) * 132 + m] = v.w;
        }
        __syncthreads();

#pragma unroll 4
        for (int k = 0; k < KC; k++) {
            const float* asr = &As[k * 132 + 4 * mg];
            ulonglong2 aA = *(const ulonglong2*)asr;
            ulonglong2 aB = *(const ulonglong2*)(asr + 64);
            const float* wsr = &Ws[(kc + k) * 132 + c0];
            float4 wf0 = *(const float4*)wsr;
            float4 wf1 = *(const float4*)(wsr + 4);
            u64 ws[8];
            ws[0] = pk(wf0.x, wf0.x); ws[1] = pk(wf0.y, wf0.y);
            ws[2] = pk(wf0.z, wf0.z); ws[3] = pk(wf0.w, wf0.w);
            ws[4] = pk(wf1.x, wf1.x); ws[5] = pk(wf1.y, wf1.y);
            ws[6] = pk(wf1.z, wf1.z); ws[7] = pk(wf1.w, wf1.w);
#pragma unroll
            for (int c = 0; c < 8; c++) {
                FMA2(acc[0][c], aA.x, ws[c]);
                FMA2(acc[1][c], aA.y, ws[c]);
                FMA2(acc[2][c], aB.x, ws[c]);
                FMA2(acc[3][c], aB.y, ws[c]);
            }
        }
    }

#pragma unroll
    for (int rp = 0; rp < 4; rp++) {
        int mloc = (rp < 2) ? (4 * mg + 2 * rp) : (64 + 4 * mg + 2 * (rp - 2));
        float lo[8], hi[8];
#pragma unroll
        for (int c = 0; c < 8; c++) upk(acc[rp][c], lo[c], hi[c]);
        size_t row = row0 + mloc;
        *(float4*)&out[row * HH + c0]           = make_float4(lo[0], lo[1], lo[2], lo[3]);
        *(float4*)&out[row * HH + c0 + 4]       = make_float4(lo[4], lo[5], lo[6], lo[7]);
        *(float4*)&out[(row + 1) * HH + c0]     = make_float4(hi[0], hi[1], hi[2], hi[3]);
        *(float4*)&out[(row + 1) * HH + c0 + 4] = make_float4(hi[4], hi[5], hi[6], hi[7]);
    }
}

// ---------------------------------------------------------------------------
// Recurrence v3: h_t = tanh(xw_t + h_{t-1} @ Whh^T). 128 CTAs x 256 threads,
// 4 batch rows per CTA. Warp w: wi = w&3 (i-block [32wi,32wi+32)), wh = w>>2
// (j-half [64wh, 64wh+64)). Lane g: r = g>>3, i0 = 32wi + 4(g&7).
// Per 2j: 1 LDS.128 dup-h quad (2 splat pairs) + 2 LDS.128 W + 4 FMA2.
// 2 warps/SMSP, chains of 64 -> latency hidden. Lane-split reduction:
// lanes with (g>>4)==wh own their outputs; the other half stores partials.
// ---------------------------------------------------------------------------
__global__ __launch_bounds__(256, 1)
void recur_kernel(const float* __restrict__ xw, const float* __restrict__ Whh,
                  float* __restrict__ seq) {
    extern __shared__ float sm[];
    float* Wt   = sm;                   // [128][132], Wt[j][i] = Whh[i][j]
    float* hd   = sm + HH * 132;        // [2][4][264] duplicated h
    float* psum = hd + 2 * 1056;        // [4 wi][4 r][32 i] partials

    const int tid = threadIdx.x;

    // Stage W transposed (coalesced LDG; one-time 4-way STS conflicts ok).
    for (int idx = tid; idx < HH * HH; idx += 256) {
        int i = idx >> 7, j = idx & 127;
        Wt[j * 132 + i] = Whh[idx];
    }
    // Zero both h buffers (incl. pads).
    for (int idx = tid; idx < 2 * 1056; idx += 256) hd[idx] = 0.0f;

    const int g   = tid & 31;
    const int w   = tid >> 5;
    const int wi  = w & 3;
    const int wh  = w >> 2;
    const int r   = g >> 3;
    const int i0  = 32 * wi + 4 * (g & 7);
    const int b   = blockIdx.x * 4 + r;
    const bool owner = ((g >> 4) == wh);
    const int j0  = 64 * wh;

    const float* wbase = Wt + i0;
    float* slot = psum + wi * 128 + r * 32 + 4 * (g & 7);

    __syncthreads();

    const float* xp = xw  + b * HH + i0;
    float*       sp = seq + b * HH + i0;

    float4 xv = make_float4(0.f, 0.f, 0.f, 0.f);
    float4 xn = xv;
    if (owner) {
        xv = *(const float4*)xp;               // t = 0
        xn = *(const float4*)(xp + BB * HH);   // t = 1
    }
    int cur = 0;

    for (int t = 0; t < SS; t++) {
        u64 acc0, acc1;
        if (owner) { acc0 = pk(xv.x, xv.y); acc1 = pk(xv.z, xv.w); }
        else       { acc0 = 0ull;           acc1 = 0ull;           }

        // prefetch xw for t+2 early (consumed next-next step)
        float4 xn2 = xn;
        if (owner && (t + 2 < SS)) xn2 = *(const float4*)(xp + (size_t)(t + 2) * BB * HH);

        const float* hr = hd + cur * 1056 + r * 264;
#pragma unroll
        for (int jj = 0; jj < 32; jj++) {
            int j = j0 + 2 * jj;
            ulonglong2 hq = *(const ulonglong2*)(hr + 2 * j);      // (hj,hj),(hj1,hj1)
            ulonglong2 w0 = *(const ulonglong2*)(wbase + j * 132);
            ulonglong2 w1 = *(const ulonglong2*)(wbase + (j + 1) * 132);
            FMA2(acc0, hq.x, w0.x);
            FMA2(acc1, hq.x, w0.y);
            FMA2(acc0, hq.y, w1.x);
            FMA2(acc1, hq.y, w1.y);
        }

        if (!owner) {
            ulonglong2 s; s.x = acc0; s.y = acc1;
            *(ulonglong2*)slot = s;
        }
        __syncthreads();

        if (owner) {
            ulonglong2 p = *(const ulonglong2*)slot;
            ADD2(acc0, p.x);
            ADD2(acc1, p.y);
            float a0, a1, a2, a3;
            upk(acc0, a0, a1); upk(acc1, a2, a3);
            float t0 = my_tanh(a0), t1 = my_tanh(a1), t2 = my_tanh(a2), t3 = my_tanh(a3);

            float* hw = hd + (cur ^ 1) * 1056 + r * 264 + 2 * i0;
            *(float4*)hw       = make_float4(t0, t0, t1, t1);
            *(float4*)(hw + 4) = make_float4(t2, t2, t3, t3);
            *(float4*)(sp + (size_t)t * BB * HH) = make_float4(t0, t1, t2, t3);

            xv = xn; xn = xn2;
        }
        __syncthreads();
        cur ^= 1;
    }
}

// ---------------------------------------------------------------------------
// FC: out[b][c] = last[b][:] . fc_w[c][:] + fc_b[c]
// ---------------------------------------------------------------------------
__global__ void fc_kernel(const float* __restrict__ last, const float* __restrict__ fw,
                          const float* __restrict__ fb, float* __restrict__ out) {
    int idx = blockIdx.x * blockDim.x + threadIdx.x;
    if (idx >= BB * NC) return;
    int b = idx / NC;
    int c = idx - b * NC;
    const float4* xr = reinterpret_cast<const float4*>(last + b * HH);
    const float4* wr = reinterpret_cast<const float4*>(fw + c * HH);
    float acc = fb[c];
#pragma unroll
    for (int j = 0; j < HH / 4; j++) {
        float4 x = __ldg(xr + j);
        float4 w = __ldg(wr + j);
        acc = fmaf(x.x, w.x, fmaf(x.y, w.y, fmaf(x.z, w.z, fmaf(x.w, w.w, acc))));
    }
    out[idx] = acc;
}

extern "C" void kernel_launch(void* const* d_in, const int* in_sizes, int n_in,
                              void* d_out, int out_size) {
    const float* x     = (const float*)d_in[0];
    const float* w_ih0 = (const float*)d_in[1];
    const float* w_hh0 = (const float*)d_in[2];
    const float* b_ih0 = (const float*)d_in[3];
    const float* b_hh0 = (const float*)d_in[4];
    const float* w_ih  = (const float*)d_in[5];   // [3][H][H]
    const float* w_hh  = (const float*)d_in[6];   // [3][H][H]
    const float* b_ih  = (const float*)d_in[7];   // [3][H]
    const float* b_hh  = (const float*)d_in[8];   // [3][H]
    const float* fc_w  = (const float*)d_in[9];
    const float* fc_b  = (const float*)d_in[10];
    float* out = (float*)d_out;

    float *bufA, *bufB, *bufC;
    cudaGetSymbolAddress((void**)&bufA, g_bufA);
    cudaGetSymbolAddress((void**)&bufB, g_bufB);
    cudaGetSymbolAddress((void**)&bufC, g_bufC);

    const size_t smP128 = (size_t)(128 * 132 + 32 * 132) * 4;            // 84.5 KB
    const size_t smP28  = (size_t)(28 * 132 + 28 * 132) * 4;             // 29.6 KB
    const size_t smR    = (size_t)(HH * 132 + 2 * 1056 + 512) * 4;       // 76.3 KB

    cudaFuncSetAttribute(proj_kernel<HH, 32, false>, cudaFuncAttributeMaxDynamicSharedMemorySize, (int)smP128);
    cudaFuncSetAttribute(proj_kernel<DIN, DIN, true>, cudaFuncAttributeMaxDynamicSharedMemorySize, (int)smP28);
    cudaFuncSetAttribute(recur_kernel, cudaFuncAttributeMaxDynamicSharedMemorySize, (int)smR);

    const int PROJ_BLOCKS = (SS * BB) / 128;   // 1024

    // Layer 0: x -> xw (bufB) -> seq (bufA)
    proj_kernel<DIN, DIN, true><<<PROJ_BLOCKS, 256, smP28>>>(x, w_ih0, b_ih0, b_hh0, bufB);
    recur_kernel<<<128, 256, smR>>>(bufB, w_hh0, bufA);

    // Layers 1..3: ping-pong A <-> C, xw always in bufB.
    float* seqs[2] = {bufA, bufC};
    for (int l = 0; l < 3; l++) {
        float* prev = seqs[l & 1];
        float* next = seqs[(l & 1) ^ 1];
        proj_kernel<HH, 32, false><<<PROJ_BLOCKS, 256, smP128>>>(
            prev, w_ih + l * HH * HH, b_ih + l * HH, b_hh + l * HH, bufB);
        recur_kernel<<<128, 256, smR>>>(bufB, w_hh + l * HH * HH, next);
    }

    // Final FC on last timestep of layer-3 output (bufC).
    const float* last = bufC + (size_t)(SS - 1) * BB * HH;
    fc_kernel<<<(BB * NC + 127) / 128, 128>>>(last, fc_w, fc_b, out);
}

// round 11
// speedup vs baseline: 1.8830x; 1.8830x over previous
#include <cuda_runtime.h>
#include <math.h>

// RNN_472446402977: 4-layer tanh RNN + FC, fp32. B=512 S=256 D_IN=28 H=128 NC=10.
// R11 = R8/R9 v4 with the misalignment fixed: psum pitch 9 -> 10 u64 so every
// ulonglong2 partial slot is 16B-aligned (pitch-9 odd-g slots trapped STS.128).
// Recurrence: W_hh entirely in REGISTERS (64 regs/lane, loaded once, zero W
// smem traffic in hot loop); h packed over 4 batch rows (float4/j -> f32x2
// row-pair multipliers load-direct); 8 j-chunk partials + symmetric 256-thread
// reduction. Crossbar model: smem charges per-lane bytes delivered.

#define BB 512
#define SS 256
#define DIN 28
#define HH 128
#define NC 10

typedef unsigned long long u64;

// Scratch (allocation-free): each [S][B][H] fp32 = 64MB.
__device__ float g_bufA[SS * BB * HH];
__device__ float g_bufB[SS * BB * HH];
__device__ float g_bufC[SS * BB * HH];

// ---- packed f32x2 helpers -------------------------------------------------
#define FMA2(acc, a, b) asm("fma.rn.f32x2 %0, %1, %2, %0;" : "+l"(acc) : "l"(a), "l"(b))
#define ADD2(acc, a)    asm("add.rn.f32x2 %0, %0, %1;"     : "+l"(acc) : "l"(a))

__device__ __forceinline__ u64 pk(float lo, float hi) {
    u64 r; asm("mov.b64 %0, {%1, %2};" : "=l"(r) : "f"(lo), "f"(hi)); return r;
}
__device__ __forceinline__ void upk(u64 v, float& lo, float& hi) {
    asm("mov.b64 {%0, %1}, %2;" : "=f"(lo), "=f"(hi) : "l"(v));
}

// Accurate tanh regardless of fast-math mapping of tanhf (~1e-6 rel).
__device__ __forceinline__ float my_tanh(float x) {
    float ax = fabsf(x);
    float e  = __expf(-2.0f * ax);
    float r  = (1.0f - e) / (1.0f + e);
    return copysignf(r, x);
}

// ---------------------------------------------------------------------------
// Projection GEMM: out[row][n] = A[row][:] . W[n][:] + bias
// 128x128 tile, 256 threads, 8x8 outputs/thread, f32x2 row-pair accumulators.
// ---------------------------------------------------------------------------
template <int K, int KC, bool SWAPPED>
__global__ __launch_bounds__(256, 2)
void proj_kernel(const float* __restrict__ A, const float* __restrict__ W,
                 const float* __restrict__ b1, const float* __restrict__ b2,
                 float* __restrict__ out) {
    extern __shared__ float sm[];
    float* Ws = sm;               // [K][132]   Ws[k][n] = W[n][k]
    float* As = sm + K * 132;     // [KC][132]  As[k][m]
    __shared__ float bs[HH];

    const int tid = threadIdx.x;

    for (int idx = tid; idx < HH * K; idx += 256) {
        int n = idx / K, k = idx - n * K;
        Ws[k * 132 + n] = W[idx];
    }
    if (tid < HH) bs[tid] = b1[tid] + b2[tid];

    const int mg = tid & 15, ng = tid >> 4;
    const int c0 = ng * 8;
    const int row0 = blockIdx.x * 128;

    __syncthreads();

    u64 acc[4][8];
#pragma unroll
    for (int c = 0; c < 8; c++) {
        float bv = bs[c0 + c];
        u64 p = pk(bv, bv);
        acc[0][c] = p; acc[1][c] = p; acc[2][c] = p; acc[3][c] = p;
    }

    for (int kc = 0; kc < K; kc += KC) {
        __syncthreads();
        for (int idx = tid; idx < 128 * (KC / 4); idx += 256) {
            int m  = idx / (KC / 4);
            int kq = idx - m * (KC / 4);
            int row = row0 + m;
            const float* src;
            if (SWAPPED) {
                int t = row >> 9, b = row & 511;   // rows are t*B+b, x is [B][S][D]
                src = A + (b * SS + t) * K + kc + 4 * kq;
            } else {
                src = A + (size_t)row * K + kc + 4 * kq;
            }
            float4 v = *(const float4*)src;
            As[(4 * kq + 0) * 132 + m] = v.x;
            As[(4 * kq + 1) * 132 + m] = v.y;
            As[(4 * kq + 2) * 132 + m] = v.z;
            As[(4 * kq + 3) * 132 + m] = v.w;
        }
        __syncthreads();

#pragma unroll 4
        for (int k = 0; k < KC; k++) {
            const float* asr = &As[k * 132 + 4 * mg];
            ulonglong2 aA = *(const ulonglong2*)asr;
            ulonglong2 aB = *(const ulonglong2*)(asr + 64);
            const float* wsr = &Ws[(kc + k) * 132 + c0];
            float4 wf0 = *(const float4*)wsr;
            float4 wf1 = *(const float4*)(wsr + 4);
            u64 ws[8];
            ws[0] = pk(wf0.x, wf0.x); ws[1] = pk(wf0.y, wf0.y);
            ws[2] = pk(wf0.z, wf0.z); ws[3] = pk(wf0.w, wf0.w);
            ws[4] = pk(wf1.x, wf1.x); ws[5] = pk(wf1.y, wf1.y);
            ws[6] = pk(wf1.z, wf1.z); ws[7] = pk(wf1.w, wf1.w);
#pragma unroll
            for (int c = 0; c < 8; c++) {
                FMA2(acc[0][c], aA.x, ws[c]);
                FMA2(acc[1][c], aA.y, ws[c]);
                FMA2(acc[2][c], aB.x, ws[c]);
                FMA2(acc[3][c], aB.y, ws[c]);
            }
        }
    }

#pragma unroll
    for (int rp = 0; rp < 4; rp++) {
        int mloc = (rp < 2) ? (4 * mg + 2 * rp) : (64 + 4 * mg + 2 * (rp - 2));
        float lo[8], hi[8];
#pragma unroll
        for (int c = 0; c < 8; c++) upk(acc[rp][c], lo[c], hi[c]);
        size_t row = row0 + mloc;
        *(float4*)&out[row * HH + c0]           = make_float4(lo[0], lo[1], lo[2], lo[3]);
        *(float4*)&out[row * HH + c0 + 4]       = make_float4(lo[4], lo[5], lo[6], lo[7]);
        *(float4*)&out[(row + 1) * HH + c0]     = make_float4(hi[0], hi[1], hi[2], hi[3]);
        *(float4*)&out[(row + 1) * HH + c0 + 4] = make_float4(hi[4], hi[5], hi[6], hi[7]);
    }
}

// ---------------------------------------------------------------------------
// Recurrence v4: h_t = tanh(xw_t + h_{t-1} @ Whh^T). 128 CTAs x 256 thr,
// 4 batch rows/CTA.
// Main phase: warp w owns j-chunk [16w,16w+16); lane g owns i in [4g,4g+4).
//   Lane holds Wreg[16][4] = Whh[i][j] in REGISTERS (loaded once).
//   Per j: 1 broadcast LDS.128 of hbuf[j] (float4 over rows; halves are the
//   f32x2 row-pair multipliers directly) + 4 W-splat movs (ALU) + 8 FMA2.
// Reduce phase: thread tid = (g2,k), k=(rp,ii): i = 4*g2+ii, rows (2rp,2rp+1).
//   Sums 8 warp partials (ADD2 tree) + packed xw, tanh x2, writes hbuf[nxt][i]
//   float2 slice + 2 seq floats. Fully symmetric, 2 barriers/step.
// psum pitch = 10 u64/lane (16B-aligned slots; pitch 9 trapped STS.128).
// Smem: 66KB staging for W^T (preload only), overlaid after by hbuf + psum.
// ---------------------------------------------------------------------------
#define PP 10    // psum lane pitch in u64 (MUST be even: ulonglong2 slots)

__global__ __launch_bounds__(256, 1)
void recur_kernel(const float* __restrict__ xw, const float* __restrict__ Whh,
                  float* __restrict__ seq) {
    extern __shared__ char smc[];
    float*  Wt   = (float*)smc;               // [128][132] staging (preload only)
    float4* hbuf = (float4*)smc;              // [2][128] h rows packed
    u64*    psum = (u64*)(smc + 4096);        // [8 w][32 g][PP] partials

    const int tid = threadIdx.x;
    const int g   = tid & 31;
    const int w   = tid >> 5;

    // --- Preload Whh^T to smem staging, then to registers -------------------
    for (int idx = tid; idx < HH * HH; idx += 256) {
        int i = idx >> 7, j = idx & 127;
        Wt[j * 132 + i] = Whh[idx];
    }
    __syncthreads();

    float Wreg[16][4];
#pragma unroll
    for (int jj = 0; jj < 16; jj++) {
        float4 v = *(const float4*)&Wt[(16 * w + jj) * 132 + 4 * g];
        Wreg[jj][0] = v.x; Wreg[jj][1] = v.y; Wreg[jj][2] = v.z; Wreg[jj][3] = v.w;
    }
    __syncthreads();

    // --- Overlay runtime smem: zero h buffers -------------------------------
    {
        float* hz = (float*)hbuf;
        for (int idx = tid; idx < 2 * 128 * 4; idx += 256) hz[idx] = 0.0f;
    }
    __syncthreads();

    // --- Reduction-phase identity -------------------------------------------
    const int g2 = tid >> 3;          // 0..31 -> i-quad
    const int k  = tid & 7;           // rp*4 + ii
    const int rp = k >> 2;
    const int ii = k & 3;
    const int ip = 4 * g2 + ii;
    const int b0 = blockIdx.x * 4;

    const size_t BHH = (size_t)BB * HH;
    const float* xq = xw  + (b0 + 2 * rp) * HH + ip;   // row 2rp; row 2rp+1 at +HH
    float*       sq = seq + (b0 + 2 * rp) * HH + ip;

    u64* pst = psum + (size_t)w * (32 * PP) + (size_t)g * PP;  // my partial slot (16B aligned)
    const u64* prd = psum + (size_t)g2 * PP + k;               // reduce base (w stride 32*PP)
    const float4* hrd = hbuf + 16 * w;                         // my j-chunk (buffer 0)

    float x0 = xq[0], x1 = xq[HH];
    int cur = 0;

    for (int t = 0; t < SS; t++) {
        // prefetch next step's xw pair
        float nx0 = 0.f, nx1 = 0.f;
        if (t + 1 < SS) { nx0 = xq[(t + 1) * BHH]; nx1 = xq[(t + 1) * BHH + HH]; }

        u64 a0[4] = {0ull, 0ull, 0ull, 0ull};   // row-pair (0,1), cols 4g+0..3
        u64 a1[4] = {0ull, 0ull, 0ull, 0ull};   // row-pair (2,3)
        const ulonglong2* hq = (const ulonglong2*)(hrd + cur * 128);
#pragma unroll
        for (int jj = 0; jj < 16; jj++) {
            ulonglong2 h4 = hq[jj];             // (h0,h1),(h2,h3) at j=16w+jj
#pragma unroll
            for (int c = 0; c < 4; c++) {
                u64 ws = pk(Wreg[jj][c], Wreg[jj][c]);
                FMA2(a0[c], h4.x, ws);
                FMA2(a1[c], h4.y, ws);
            }
        }
        // store partials: slot order = rp*4 + ii (all 16B-aligned with PP=10)
        ulonglong2 s;
        s.x = a0[0]; s.y = a0[1]; *(ulonglong2*)(pst + 0) = s;
        s.x = a0[2]; s.y = a0[3]; *(ulonglong2*)(pst + 2) = s;
        s.x = a1[0]; s.y = a1[1]; *(ulonglong2*)(pst + 4) = s;
        s.x = a1[2]; s.y = a1[3]; *(ulonglong2*)(pst + 6) = s;
        __syncthreads();

        // reduce 8 warp partials (tree) + xw
        u64 p0 = prd[0 * 32 * PP], p1 = prd[1 * 32 * PP], p2 = prd[2 * 32 * PP], p3 = prd[3 * 32 * PP];
        u64 p4 = prd[4 * 32 * PP], p5 = prd[5 * 32 * PP], p6 = prd[6 * 32 * PP], p7 = prd[7 * 32 * PP];
        ADD2(p0, p1); ADD2(p2, p3); ADD2(p4, p5); ADD2(p6, p7);
        ADD2(p0, p2); ADD2(p4, p6);
        ADD2(p0, p4);
        ADD2(p0, pk(x0, x1));

        float v0, v1; upk(p0, v0, v1);
        float t0 = my_tanh(v0), t1 = my_tanh(v1);

        // write h for next step: hbuf[nxt][ip], rows (2rp, 2rp+1)
        float* hw = (float*)(hbuf + (cur ^ 1) * 128 + ip) + 2 * rp;
        hw[0] = t0; hw[1] = t1;
        // write sequence output
        sq[(size_t)t * BHH]      = t0;
        sq[(size_t)t * BHH + HH] = t1;

        x0 = nx0; x1 = nx1;
        __syncthreads();
        cur ^= 1;
    }
}

// ---------------------------------------------------------------------------
// FC: out[b][c] = last[b][:] . fc_w[c][:] + fc_b[c]
// ---------------------------------------------------------------------------
__global__ void fc_kernel(const float* __restrict__ last, const float* __restrict__ fw,
                          const float* __restrict__ fb, float* __restrict__ out) {
    int idx = blockIdx.x * blockDim.x + threadIdx.x;
    if (idx >= BB * NC) return;
    int b = idx / NC;
    int c = idx - b * NC;
    const float4* xr = reinterpret_cast<const float4*>(last + b * HH);
    const float4* wr = reinterpret_cast<const float4*>(fw + c * HH);
    float acc = fb[c];
#pragma unroll
    for (int j = 0; j < HH / 4; j++) {
        float4 x = __ldg(xr + j);
        float4 w = __ldg(wr + j);
        acc = fmaf(x.x, w.x, fmaf(x.y, w.y, fmaf(x.z, w.z, fmaf(x.w, w.w, acc))));
    }
    out[idx] = acc;
}

extern "C" void kernel_launch(void* const* d_in, const int* in_sizes, int n_in,
                              void* d_out, int out_size) {
    const float* x     = (const float*)d_in[0];
    const float* w_ih0 = (const float*)d_in[1];
    const float* w_hh0 = (const float*)d_in[2];
    const float* b_ih0 = (const float*)d_in[3];
    const float* b_hh0 = (const float*)d_in[4];
    const float* w_ih  = (const float*)d_in[5];   // [3][H][H]
    const float* w_hh  = (const float*)d_in[6];   // [3][H][H]
    const float* b_ih  = (const float*)d_in[7];   // [3][H]
    const float* b_hh  = (const float*)d_in[8];   // [3][H]
    const float* fc_w  = (const float*)d_in[9];
    const float* fc_b  = (const float*)d_in[10];
    float* out = (float*)d_out;

    float *bufA, *bufB, *bufC;
    cudaGetSymbolAddress((void**)&bufA, g_bufA);
    cudaGetSymbolAddress((void**)&bufB, g_bufB);
    cudaGetSymbolAddress((void**)&bufC, g_bufC);

    const size_t smP128 = (size_t)(128 * 132 + 32 * 132) * 4;   // 84.5 KB
    const size_t smP28  = (size_t)(28 * 132 + 28 * 132) * 4;    // 29.6 KB
    const size_t smR    = (size_t)(128 * 132) * 4;              // 67.6 KB (staging; runtime overlaid)

    cudaFuncSetAttribute(proj_kernel<HH, 32, false>, cudaFuncAttributeMaxDynamicSharedMemorySize, (int)smP128);
    cudaFuncSetAttribute(proj_kernel<DIN, DIN, true>, cudaFuncAttributeMaxDynamicSharedMemorySize, (int)smP28);
    cudaFuncSetAttribute(recur_kernel, cudaFuncAttributeMaxDynamicSharedMemorySize, (int)smR);

    const int PROJ_BLOCKS = (SS * BB) / 128;   // 1024

    // Layer 0: x -> xw (bufB) -> seq (bufA)
    proj_kernel<DIN, DIN, true><<<PROJ_BLOCKS, 256, smP28>>>(x, w_ih0, b_ih0, b_hh0, bufB);
    recur_kernel<<<128, 256, smR>>>(bufB, w_hh0, bufA);

    // Layers 1..3: ping-pong A <-> C, xw always in bufB.
    float* seqs[2] = {bufA, bufC};
    for (int l = 0; l < 3; l++) {
        float* prev = seqs[l & 1];
        float* next = seqs[(l & 1) ^ 1];
        proj_kernel<HH, 32, false><<<PROJ_BLOCKS, 256, smP128>>>(
            prev, w_ih + l * HH * HH, b_ih + l * HH, b_hh + l * HH, bufB);
        recur_kernel<<<128, 256, smR>>>(bufB, w_hh + l * HH * HH, next);
    }

    // Final FC on last timestep of layer-3 output (bufC).
    const float* last = bufC + (size_t)(SS - 1) * BB * HH;
    fc_kernel<<<(BB * NC + 127) / 128, 128>>>(last, fc_w, fc_b, out);
}

// round 12
// speedup vs baseline: 1.9390x; 1.0297x over previous
#include <cuda_runtime.h>
#include <math.h>

// RNN_472446402977: 4-layer tanh RNN + FC, fp32. B=512 S=256 D_IN=28 H=128 NC=10.
// R12: recurrence v5 — 2 batch rows/CTA, grid=256, 2 CTAs/SM (4 warps/SMSP for
// stall hiding, all 148 SMs used). W_hh in registers as native (i,i+1) u64
// pairs (zero per-step W packing). Same FMA/crossbar floors as v4, less stall.

#define BB 512
#define SS 256
#define DIN 28
#define HH 128
#define NC 10

typedef unsigned long long u64;

// Scratch (allocation-free): each [S][B][H] fp32 = 64MB.
__device__ float g_bufA[SS * BB * HH];
__device__ float g_bufB[SS * BB * HH];
__device__ float g_bufC[SS * BB * HH];

// ---- packed f32x2 helpers -------------------------------------------------
#define FMA2(acc, a, b) asm("fma.rn.f32x2 %0, %1, %2, %0;" : "+l"(acc) : "l"(a), "l"(b))
#define ADD2(acc, a)    asm("add.rn.f32x2 %0, %0, %1;"     : "+l"(acc) : "l"(a))

__device__ __forceinline__ u64 pk(float lo, float hi) {
    u64 r; asm("mov.b64 %0, {%1, %2};" : "=l"(r) : "f"(lo), "f"(hi)); return r;
}
__device__ __forceinline__ void upk(u64 v, float& lo, float& hi) {
    asm("mov.b64 {%0, %1}, %2;" : "=f"(lo), "=f"(hi) : "l"(v));
}

// Accurate tanh regardless of fast-math mapping of tanhf (~1e-6 rel).
__device__ __forceinline__ float my_tanh(float x) {
    float ax = fabsf(x);
    float e  = __expf(-2.0f * ax);
    float r  = (1.0f - e) / (1.0f + e);
    return copysignf(r, x);
}

// ---------------------------------------------------------------------------
// Projection GEMM: out[row][n] = A[row][:] . W[n][:] + bias
// 128x128 tile, 256 threads, 8x8 outputs/thread, f32x2 row-pair accumulators.
// ---------------------------------------------------------------------------
template <int K, int KC, bool SWAPPED>
__global__ __launch_bounds__(256, 2)
void proj_kernel(const float* __restrict__ A, const float* __restrict__ W,
                 const float* __restrict__ b1, const float* __restrict__ b2,
                 float* __restrict__ out) {
    extern __shared__ float sm[];
    float* Ws = sm;               // [K][132]   Ws[k][n] = W[n][k]
    float* As = sm + K * 132;     // [KC][132]  As[k][m]
    __shared__ float bs[HH];

    const int tid = threadIdx.x;

    // Stage W transposed with float4 global reads.
    for (int idx = tid; idx < HH * (K / 4); idx += 256) {
        int n  = idx / (K / 4);
        int kq = idx - n * (K / 4);
        float4 v = *(const float4*)&W[n * K + 4 * kq];
        Ws[(4 * kq + 0) * 132 + n] = v.x;
        Ws[(4 * kq + 1) * 132 + n] = v.y;
        Ws[(4 * kq + 2) * 132 + n] = v.z;
        Ws[(4 * kq + 3) * 132 + n] = v.w;
    }
    if (tid < HH) bs[tid] = b1[tid] + b2[tid];

    const int mg = tid & 15, ng = tid >> 4;
    const int c0 = ng * 8;
    const int row0 = blockIdx.x * 128;

    __syncthreads();

    u64 acc[4][8];
#pragma unroll
    for (int c = 0; c < 8; c++) {
        float bv = bs[c0 + c];
        u64 p = pk(bv, bv);
        acc[0][c] = p; acc[1][c] = p; acc[2][c] = p; acc[3][c] = p;
    }

    for (int kc = 0; kc < K; kc += KC) {
        __syncthreads();
        for (int idx = tid; idx < 128 * (KC / 4); idx += 256) {
            int m  = idx / (KC / 4);
            int kq = idx - m * (KC / 4);
            int row = row0 + m;
            const float* src;
            if (SWAPPED) {
                int t = row >> 9, b = row & 511;   // rows are t*B+b, x is [B][S][D]
                src = A + (b * SS + t) * K + kc + 4 * kq;
            } else {
                src = A + (size_t)row * K + kc + 4 * kq;
            }
            float4 v = *(const float4*)src;
            As[(4 * kq + 0) * 132 + m] = v.x;
            As[(4 * kq + 1) * 132 + m] = v.y;
            As[(4 * kq + 2) * 132 + m] = v.z;
            As[(4 * kq + 3) * 132 + m] = v.w;
        }
        __syncthreads();

#pragma unroll 4
        for (int k = 0; k < KC; k++) {
            const float* asr = &As[k * 132 + 4 * mg];
            ulonglong2 aA = *(const ulonglong2*)asr;
            ulonglong2 aB = *(const ulonglong2*)(asr + 64);
            const float* wsr = &Ws[(kc + k) * 132 + c0];
            float4 wf0 = *(const float4*)wsr;
            float4 wf1 = *(const float4*)(wsr + 4);
            u64 ws[8];
            ws[0] = pk(wf0.x, wf0.x); ws[1] = pk(wf0.y, wf0.y);
            ws[2] = pk(wf0.z, wf0.z); ws[3] = pk(wf0.w, wf0.w);
            ws[4] = pk(wf1.x, wf1.x); ws[5] = pk(wf1.y, wf1.y);
            ws[6] = pk(wf1.z, wf1.z); ws[7] = pk(wf1.w, wf1.w);
#pragma unroll
            for (int c = 0; c < 8; c++) {
                FMA2(acc[0][c], aA.x, ws[c]);
                FMA2(acc[1][c], aA.y, ws[c]);
                FMA2(acc[2][c], aB.x, ws[c]);
                FMA2(acc[3][c], aB.y, ws[c]);
            }
        }
    }

#pragma unroll
    for (int rp = 0; rp < 4; rp++) {
        int mloc = (rp < 2) ? (4 * mg + 2 * rp) : (64 + 4 * mg + 2 * (rp - 2));
        float lo[8], hi[8];
#pragma unroll
        for (int c = 0; c < 8; c++) upk(acc[rp][c], lo[c], hi[c]);
        size_t row = row0 + mloc;
        *(float4*)&out[row * HH + c0]           = make_float4(lo[0], lo[1], lo[2], lo[3]);
        *(float4*)&out[row * HH + c0 + 4]       = make_float4(lo[4], lo[5], lo[6], lo[7]);
        *(float4*)&out[(row + 1) * HH + c0]     = make_float4(hi[0], hi[1], hi[2], hi[3]);
        *(float4*)&out[(row + 1) * HH + c0 + 4] = make_float4(hi[4], hi[5], hi[6], hi[7]);
    }
}

// ---------------------------------------------------------------------------
// Recurrence v5: h_t = tanh(xw_t + h_{t-1} @ Whh^T). 256 CTAs x 256 thr,
// 2 batch rows/CTA, 2 CTAs/SM (launch_bounds(256,2)).
// Compute: warp w owns j-chunk [16w,16w+16); lane g owns i-quad [4g,4g+4).
//   Wu[jj][p] = (Whh[4g+2p][j], Whh[4g+2p+1][j]) u64 in regs (loaded once).
//   Per jj: LDS.64 h2=(h_r0,h_r1) broadcast + 2 splat movs + 4 FMA2 into
//   acc[p][r] = (out[4g+2p],out[4g+2p+1]) for row r.
// Partials: psum[w][g][slot 2r+p], pitch 6 u64 (STS.128 conflict-free).
// Reduce (threads 0..127): r = t>>6, P = t&63 -> i=(2P,2P+1): 8 LDS.64 tree
//   + xw (LDG.64) + tanh x2 -> hbuf[nxt] + seq STG.64. 2 barriers/step.
// ---------------------------------------------------------------------------
__global__ __launch_bounds__(256, 2)
void recur2_kernel(const float* __restrict__ xw, const float* __restrict__ Whh,
                   float* __restrict__ seq) {
    extern __shared__ char smc[];
    float*  Wt   = (float*)smc;            // [128][132] staging (preload only)
    float*  hbuf = (float*)smc;            // [2][128][2] (h_r0,h_r1) pairs
    u64*    psum = (u64*)(smc + 2048);     // [8 w][32 g][6] partials

    const int tid = threadIdx.x;
    const int g   = tid & 31;
    const int w   = tid >> 5;

    // --- Stage Whh^T to smem, then native (i,i+1) u64 pairs to registers ----
    for (int idx = tid; idx < HH * (HH / 4); idx += 256) {
        int i  = idx / 32;
        int jq = idx - i * 32;
        float4 v = *(const float4*)&Whh[i * HH + 4 * jq];
        Wt[(4 * jq + 0) * 132 + i] = v.x;
        Wt[(4 * jq + 1) * 132 + i] = v.y;
        Wt[(4 * jq + 2) * 132 + i] = v.z;
        Wt[(4 * jq + 3) * 132 + i] = v.w;
    }
    __syncthreads();

    u64 Wu[16][2];
#pragma unroll
    for (int jj = 0; jj < 16; jj++) {
        float4 v = *(const float4*)&Wt[(16 * w + jj) * 132 + 4 * g];
        Wu[jj][0] = pk(v.x, v.y);
        Wu[jj][1] = pk(v.z, v.w);
    }
    __syncthreads();

    // --- Overlay runtime smem: zero both h buffers --------------------------
    for (int idx = tid; idx < 2 * 128 * 2; idx += 256) hbuf[idx] = 0.0f;
    __syncthreads();

    // --- Reducer identity (threads 0..127) ----------------------------------
    const int r  = tid >> 6;           // 0 or 1 (valid for tid<128)
    const int P  = tid & 63;           // i-pair index: i = 2P, 2P+1
    const int b0 = blockIdx.x * 2;
    const bool red = (tid < 128);

    const size_t BHH = (size_t)BB * HH;
    const float* xq = xw  + (size_t)(b0 + r) * HH + 2 * P;
    float*       sq = seq + (size_t)(b0 + r) * HH + 2 * P;

    u64* pst = psum + (size_t)w * 192 + (size_t)g * 6;   // my partial slots
    const u64* prd = psum + (size_t)(P >> 1) * 6 + 2 * r + (P & 1); // + w*192

    float2 xv = make_float2(0.f, 0.f);
    if (red) xv = *(const float2*)xq;      // xw at t=0
    int cur = 0;

    for (int t = 0; t < SS; t++) {
        // prefetch next step's xw
        float2 xn = make_float2(0.f, 0.f);
        if (red && (t + 1 < SS)) xn = *(const float2*)(xq + (size_t)(t + 1) * BHH);

        u64 a00 = 0ull, a10 = 0ull, a01 = 0ull, a11 = 0ull;  // acc[p][r]
        const float* hr = hbuf + cur * 256;
#pragma unroll
        for (int jj = 0; jj < 16; jj++) {
            float2 h2 = *(const float2*)(hr + 2 * (16 * w + jj));  // (h_r0,h_r1)
            u64 s0 = pk(h2.x, h2.x);
            u64 s1 = pk(h2.y, h2.y);
            FMA2(a00, s0, Wu[jj][0]);
            FMA2(a10, s0, Wu[jj][1]);
            FMA2(a01, s1, Wu[jj][0]);
            FMA2(a11, s1, Wu[jj][1]);
        }
        // store partials: slots (2r+p): +0:(r0,p0) +1:(r0,p1) +2:(r1,p0) +3:(r1,p1)
        ulonglong2 s;
        s.x = a00; s.y = a10; *(ulonglong2*)(pst + 0) = s;
        s.x = a01; s.y = a11; *(ulonglong2*)(pst + 2) = s;
        __syncthreads();

        if (red) {
            u64 p0 = prd[0 * 192], p1 = prd[1 * 192], p2 = prd[2 * 192], p3 = prd[3 * 192];
            u64 p4 = prd[4 * 192], p5 = prd[5 * 192], p6 = prd[6 * 192], p7 = prd[7 * 192];
            ADD2(p0, p1); ADD2(p2, p3); ADD2(p4, p5); ADD2(p6, p7);
            ADD2(p0, p2); ADD2(p4, p6);
            ADD2(p0, p4);
            ADD2(p0, pk(xv.x, xv.y));

            float v0, v1; upk(p0, v0, v1);
            float t0 = my_tanh(v0), t1 = my_tanh(v1);

            // h for next step: hbuf[nxt][i].component r
            float* hw = hbuf + (cur ^ 1) * 256;
            hw[4 * P + r]     = t0;     // i = 2P
            hw[4 * P + 2 + r] = t1;     // i = 2P+1
            // sequence output (STG.64)
            *(float2*)(sq + (size_t)t * BHH) = make_float2(t0, t1);
            xv = xn;
        }
        __syncthreads();
        cur ^= 1;
    }
}

// ---------------------------------------------------------------------------
// FC: out[b][c] = last[b][:] . fc_w[c][:] + fc_b[c]
// ---------------------------------------------------------------------------
__global__ void fc_kernel(const float* __restrict__ last, const float* __restrict__ fw,
                          const float* __restrict__ fb, float* __restrict__ out) {
    int idx = blockIdx.x * blockDim.x + threadIdx.x;
    if (idx >= BB * NC) return;
    int b = idx / NC;
    int c = idx - b * NC;
    const float4* xr = reinterpret_cast<const float4*>(last + b * HH);
    const float4* wr = reinterpret_cast<const float4*>(fw + c * HH);
    float acc = fb[c];
#pragma unroll
    for (int j = 0; j < HH / 4; j++) {
        float4 x = __ldg(xr + j);
        float4 w = __ldg(wr + j);
        acc = fmaf(x.x, w.x, fmaf(x.y, w.y, fmaf(x.z, w.z, fmaf(x.w, w.w, acc))));
    }
    out[idx] = acc;
}

extern "C" void kernel_launch(void* const* d_in, const int* in_sizes, int n_in,
                              void* d_out, int out_size) {
    const float* x     = (const float*)d_in[0];
    const float* w_ih0 = (const float*)d_in[1];
    const float* w_hh0 = (const float*)d_in[2];
    const float* b_ih0 = (const float*)d_in[3];
    const float* b_hh0 = (const float*)d_in[4];
    const float* w_ih  = (const float*)d_in[5];   // [3][H][H]
    const float* w_hh  = (const float*)d_in[6];   // [3][H][H]
    const float* b_ih  = (const float*)d_in[7];   // [3][H]
    const float* b_hh  = (const float*)d_in[8];   // [3][H]
    const float* fc_w  = (const float*)d_in[9];
    const float* fc_b  = (const float*)d_in[10];
    float* out = (float*)d_out;

    float *bufA, *bufB, *bufC;
    cudaGetSymbolAddress((void**)&bufA, g_bufA);
    cudaGetSymbolAddress((void**)&bufB, g_bufB);
    cudaGetSymbolAddress((void**)&bufC, g_bufC);

    const size_t smP128 = (size_t)(128 * 132 + 64 * 132) * 4;   // 101.4 KB (KC=64)
    const size_t smP28  = (size_t)(28 * 132 + 28 * 132) * 4;    // 29.6 KB
    const size_t smR    = (size_t)(128 * 132) * 4;              // 67.6 KB (staging; overlaid)

    cudaFuncSetAttribute(proj_kernel<HH, 64, false>, cudaFuncAttributeMaxDynamicSharedMemorySize, (int)smP128);
    cudaFuncSetAttribute(proj_kernel<DIN, DIN, true>, cudaFuncAttributeMaxDynamicSharedMemorySize, (int)smP28);
    cudaFuncSetAttribute(recur2_kernel, cudaFuncAttributeMaxDynamicSharedMemorySize, (int)smR);

    const int PROJ_BLOCKS = (SS * BB) / 128;   // 1024

    // Layer 0: x -> xw (bufB) -> seq (bufA)
    proj_kernel<DIN, DIN, true><<<PROJ_BLOCKS, 256, smP28>>>(x, w_ih0, b_ih0, b_hh0, bufB);
    recur2_kernel<<<256, 256, smR>>>(bufB, w_hh0, bufA);

    // Layers 1..3: ping-pong A <-> C, xw always in bufB.
    float* seqs[2] = {bufA, bufC};
    for (int l = 0; l < 3; l++) {
        float* prev = seqs[l & 1];
        float* next = seqs[(l & 1) ^ 1];
        proj_kernel<HH, 64, false><<<PROJ_BLOCKS, 256, smP128>>>(
            prev, w_ih + l * HH * HH, b_ih + l * HH, b_hh + l * HH, bufB);
        recur2_kernel<<<256, 256, smR>>>(bufB, w_hh + l * HH * HH, next);
    }

    // Final FC on last timestep of layer-3 output (bufC).
    const float* last = bufC + (size_t)(SS - 1) * BB * HH;
    fc_kernel<<<(BB * NC + 127) / 128, 128>>>(last, fc_w, fc_b, out);
}